// round 1
// baseline (speedup 1.0000x reference)
#include <cuda_runtime.h>
#include <cuda_fp16.h>
#include <cstdint>

#define K_DIM 1024
#define O_DIM 1024
#define FP8_MAX_F 448.0f

#define BM 128
#define BN 128
#define BK 32
#define LDA 40  // BK + 8 pad (halves); 80B row stride, 16B-aligned, conflict-free frag loads

// ---- scratch (static device globals; no runtime allocation) ----
__device__ unsigned int g_amax_bits;
__device__ float  g_wscale[O_DIM];
__device__ __half g_wq[(size_t)O_DIM * K_DIM];
__device__ __half g_xq[(size_t)32768 * K_DIM];

// ---------------- kernel 0: reset ----------------
__global__ void reset_kernel() { g_amax_bits = 0u; }

// ---------------- kernel 1: global amax of x ----------------
__global__ void amax_kernel(const float* __restrict__ x, int n4) {
    const float4* x4 = (const float4*)x;
    float m = 0.f;
    int stride = gridDim.x * blockDim.x;
    for (int j = blockIdx.x * blockDim.x + threadIdx.x; j < n4; j += stride) {
        float4 v = x4[j];
        m = fmaxf(m, fmaxf(fmaxf(fabsf(v.x), fabsf(v.y)), fmaxf(fabsf(v.z), fabsf(v.w))));
    }
    #pragma unroll
    for (int o = 16; o; o >>= 1) m = fmaxf(m, __shfl_xor_sync(0xffffffffu, m, o));
    __shared__ float sm[8];
    if ((threadIdx.x & 31) == 0) sm[threadIdx.x >> 5] = m;
    __syncthreads();
    if (threadIdx.x < 32) {
        m = (threadIdx.x < (blockDim.x >> 5)) ? sm[threadIdx.x] : 0.f;
        #pragma unroll
        for (int o = 4; o; o >>= 1) m = fmaxf(m, __shfl_xor_sync(0xffffffffu, m, o));
        if (threadIdx.x == 0) atomicMax(&g_amax_bits, __float_as_uint(m));
    }
}

// ---------------- kernel 2: per-row weight amax + quantize to fp16 ----------------
__global__ void wq_kernel(const float* __restrict__ w) {
    int row = blockIdx.x;
    const float* wr = w + (size_t)row * K_DIM;
    float m = 0.f;
    for (int k = threadIdx.x; k < K_DIM; k += 128) m = fmaxf(m, fabsf(wr[k]));
    #pragma unroll
    for (int o = 16; o; o >>= 1) m = fmaxf(m, __shfl_xor_sync(0xffffffffu, m, o));
    __shared__ float sm[4];
    if ((threadIdx.x & 31) == 0) sm[threadIdx.x >> 5] = m;
    __syncthreads();
    float am = fmaxf(fmaxf(sm[0], sm[1]), fmaxf(sm[2], sm[3]));
    float scale = fmaxf(__fdiv_rn(am, FP8_MAX_F), 1e-12f);
    if (threadIdx.x == 0) g_wscale[row] = scale;
    for (int k = threadIdx.x; k < K_DIM; k += 128) {
        float q = rintf(fminf(fmaxf(__fdiv_rn(wr[k], scale), -FP8_MAX_F), FP8_MAX_F));
        g_wq[(size_t)row * K_DIM + k] = __float2half_rn(q);  // exact (integer <= 448)
    }
}

// ---------------- kernel 3: quantize x to fp16 ----------------
__global__ void xq_kernel(const float* __restrict__ x, int n4) {
    float scale = fmaxf(__fdiv_rn(__uint_as_float(g_amax_bits), FP8_MAX_F), 1e-12f);
    const float4* x4 = (const float4*)x;
    int stride = gridDim.x * blockDim.x;
    for (int j = blockIdx.x * blockDim.x + threadIdx.x; j < n4; j += stride) {
        float4 v = x4[j];
        float q0 = rintf(fminf(fmaxf(__fdiv_rn(v.x, scale), -FP8_MAX_F), FP8_MAX_F));
        float q1 = rintf(fminf(fmaxf(__fdiv_rn(v.y, scale), -FP8_MAX_F), FP8_MAX_F));
        float q2 = rintf(fminf(fmaxf(__fdiv_rn(v.z, scale), -FP8_MAX_F), FP8_MAX_F));
        float q3 = rintf(fminf(fmaxf(__fdiv_rn(v.w, scale), -FP8_MAX_F), FP8_MAX_F));
        __half2 h0 = __floats2half2_rn(q0, q1);
        __half2 h1 = __floats2half2_rn(q2, q3);
        uint2 u;
        u.x = *reinterpret_cast<unsigned int*>(&h0);
        u.y = *reinterpret_cast<unsigned int*>(&h1);
        *reinterpret_cast<uint2*>(&g_xq[(size_t)j * 4]) = u;
    }
}

// ---------------- kernel 4: fp16 tensor-core GEMM + dequant epilogue ----------------
// out[t, o] = acc(t,o) * (iscale * wscale[o]) + bias[o]
__global__ void __launch_bounds__(256, 2)
gemm_kernel(const float* __restrict__ bias, float* __restrict__ out) {
    __shared__ __align__(16) __half As[BM * LDA];
    __shared__ __align__(16) __half Bs[BN * LDA];

    const int tid  = threadIdx.x;
    const int bm   = blockIdx.y * BM;
    const int bn   = blockIdx.x * BN;
    const int wid  = tid >> 5, lane = tid & 31;
    const int wm   = wid >> 2, wn = wid & 3;     // 2x4 warp grid, warp tile 64x32
    const int g    = lane >> 2, t4 = lane & 3;

    const __half* Ag = g_xq + (size_t)bm * K_DIM;
    const __half* Bg = g_wq + (size_t)bn * K_DIM;

    const int ar = tid >> 2;          // 0..63
    const int ac = (tid & 3) * 8;     // 0,8,16,24

    float acc[4][4][4];
    #pragma unroll
    for (int i = 0; i < 4; i++)
        #pragma unroll
        for (int j = 0; j < 4; j++)
            #pragma unroll
            for (int r = 0; r < 4; r++) acc[i][j][r] = 0.f;

    int4 ra0, ra1, rb0, rb1;

#define LOADG(kt) do { \
    ra0 = *(const int4*)(Ag + (size_t)(ar)      * K_DIM + (kt) * BK + ac); \
    ra1 = *(const int4*)(Ag + (size_t)(ar + 64) * K_DIM + (kt) * BK + ac); \
    rb0 = *(const int4*)(Bg + (size_t)(ar)      * K_DIM + (kt) * BK + ac); \
    rb1 = *(const int4*)(Bg + (size_t)(ar + 64) * K_DIM + (kt) * BK + ac); \
} while (0)

#define STORES() do { \
    *(int4*)&As[ar * LDA + ac]        = ra0; \
    *(int4*)&As[(ar + 64) * LDA + ac] = ra1; \
    *(int4*)&Bs[ar * LDA + ac]        = rb0; \
    *(int4*)&Bs[(ar + 64) * LDA + ac] = rb1; \
} while (0)

    LOADG(0);
    STORES();
    __syncthreads();

    const int NT = K_DIM / BK;  // 32
    for (int kt = 1; kt <= NT; kt++) {
        if (kt < NT) LOADG(kt);   // prefetch next tile to registers

        #pragma unroll
        for (int kk = 0; kk < BK; kk += 16) {
            uint32_t a[4][4], b[4][2];
            #pragma unroll
            for (int im = 0; im < 4; im++) {
                const __half* p = &As[(wm * 64 + im * 16 + g) * LDA + kk + t4 * 2];
                a[im][0] = *(const uint32_t*)p;
                a[im][1] = *(const uint32_t*)(p + 8 * LDA);
                a[im][2] = *(const uint32_t*)(p + 8);
                a[im][3] = *(const uint32_t*)(p + 8 * LDA + 8);
            }
            #pragma unroll
            for (int in_ = 0; in_ < 4; in_++) {
                const __half* p = &Bs[(wn * 32 + in_ * 8 + g) * LDA + kk + t4 * 2];
                b[in_][0] = *(const uint32_t*)p;
                b[in_][1] = *(const uint32_t*)(p + 8);
            }
            #pragma unroll
            for (int im = 0; im < 4; im++)
                #pragma unroll
                for (int in_ = 0; in_ < 4; in_++) {
                    float* c = acc[im][in_];
                    asm volatile(
                        "mma.sync.aligned.m16n8k16.row.col.f32.f16.f16.f32 "
                        "{%0,%1,%2,%3}, {%4,%5,%6,%7}, {%8,%9}, {%0,%1,%2,%3};\n"
                        : "+f"(c[0]), "+f"(c[1]), "+f"(c[2]), "+f"(c[3])
                        : "r"(a[im][0]), "r"(a[im][1]), "r"(a[im][2]), "r"(a[im][3]),
                          "r"(b[in_][0]), "r"(b[in_][1]));
                }
        }
        __syncthreads();
        if (kt < NT) {
            STORES();
            __syncthreads();
        }
    }
#undef LOADG
#undef STORES

    // epilogue: dequant + bias
    const float iscale = fmaxf(__fdiv_rn(__uint_as_float(g_amax_bits), FP8_MAX_F), 1e-12f);
    #pragma unroll
    for (int in_ = 0; in_ < 4; in_++) {
        int col = bn + wn * 32 + in_ * 8 + t4 * 2;
        float s0 = iscale * g_wscale[col];
        float s1 = iscale * g_wscale[col + 1];
        float b0 = bias[col];
        float b1 = bias[col + 1];
        #pragma unroll
        for (int im = 0; im < 4; im++) {
            int row = bm + wm * 64 + im * 16 + g;
            float* c = acc[im][in_];
            float2 v0 = make_float2(c[0] * s0 + b0, c[1] * s1 + b1);
            float2 v1 = make_float2(c[2] * s0 + b0, c[3] * s1 + b1);
            *(float2*)&out[(size_t)row * O_DIM + col]       = v0;
            *(float2*)&out[(size_t)(row + 8) * O_DIM + col] = v1;
        }
    }
}

// ---------------- launch ----------------
extern "C" void kernel_launch(void* const* d_in, const int* in_sizes, int n_in,
                              void* d_out, int out_size) {
    const float* x    = (const float*)d_in[0];   // [T, 1024]
    const float* w    = (const float*)d_in[1];   // [1024, 1024]
    const float* bias = (const float*)d_in[2];   // [1024]
    float* out = (float*)d_out;                  // [T, 1024] fp32

    const int n  = in_sizes[0];
    const int n4 = n / 4;
    const int T  = n / K_DIM;                    // 32768

    reset_kernel<<<1, 1>>>();
    amax_kernel<<<1184, 256>>>(x, n4);
    wq_kernel<<<O_DIM, 128>>>(w);
    xq_kernel<<<2048, 256>>>(x, n4);

    dim3 grid(O_DIM / BN, T / BM);               // (8, 256)
    gemm_kernel<<<grid, 256>>>(bias, out);
}

// round 6
// speedup vs baseline: 1.2677x; 1.2677x over previous
#include <cuda_runtime.h>
#include <cuda_fp16.h>
#include <cstdint>

#define K_DIM 1024
#define O_DIM 1024
#define FP8_MAX_F 448.0f

// ---- GEMM tiling (HMMA mma.sync path; tcgen05 unavailable at compute_103) ----
#define BM 128
#define BN 128
#define BK 64                  // 128 bytes/row fp16 = one SW128 atom
#define STAGES 3
#define NT (K_DIM / BK)        // 16

#define A_STAGE_BYTES (BM * 128)                        // 16384
#define B_STAGE_BYTES (BN * 128)                        // 16384
#define STAGE_BYTES   (A_STAGE_BYTES + B_STAGE_BYTES)   // 32768
#define SMEM_TOTAL    (STAGES * STAGE_BYTES)            // 98304

static __device__ __forceinline__ uint32_t sw128(uint32_t off) {
    return off ^ ((off >> 3) & 0x70);
}
static __device__ __forceinline__ uint32_t smem_u32(const void* p) {
    uint32_t a;
    asm("{ .reg .u64 t; cvta.to.shared.u64 t, %1; cvt.u32.u64 %0, t; }" : "=r"(a) : "l"(p));
    return a;
}

// ---- scratch (static device globals; no runtime allocation) ----
__device__ unsigned int g_amax_bits;
__device__ float  g_wscale[O_DIM];
__device__ __half g_wq[(size_t)O_DIM * K_DIM];
__device__ __half g_xq[(size_t)32768 * K_DIM];

// ---------------- kernel 0: reset ----------------
__global__ void reset_kernel() { g_amax_bits = 0u; }

// ---------------- kernel 1: global amax of x ----------------
__global__ void amax_kernel(const float* __restrict__ x, int n4) {
    const float4* x4 = (const float4*)x;
    float m = 0.f;
    int stride = gridDim.x * blockDim.x;
    for (int j = blockIdx.x * blockDim.x + threadIdx.x; j < n4; j += stride) {
        float4 v = x4[j];
        m = fmaxf(m, fmaxf(fmaxf(fabsf(v.x), fabsf(v.y)), fmaxf(fabsf(v.z), fabsf(v.w))));
    }
    #pragma unroll
    for (int o = 16; o; o >>= 1) m = fmaxf(m, __shfl_xor_sync(0xffffffffu, m, o));
    __shared__ float sm[8];
    if ((threadIdx.x & 31) == 0) sm[threadIdx.x >> 5] = m;
    __syncthreads();
    if (threadIdx.x < 32) {
        m = (threadIdx.x < (blockDim.x >> 5)) ? sm[threadIdx.x] : 0.f;
        #pragma unroll
        for (int o = 4; o; o >>= 1) m = fmaxf(m, __shfl_xor_sync(0xffffffffu, m, o));
        if (threadIdx.x == 0) atomicMax(&g_amax_bits, __float_as_uint(m));
    }
}

// ---------------- kernel 2: per-row weight amax + quantize to fp16 ----------------
__global__ void wq_kernel(const float* __restrict__ w) {
    int row = blockIdx.x;
    const float* wr = w + (size_t)row * K_DIM;
    float m = 0.f;
    for (int k = threadIdx.x; k < K_DIM; k += 128) m = fmaxf(m, fabsf(wr[k]));
    #pragma unroll
    for (int o = 16; o; o >>= 1) m = fmaxf(m, __shfl_xor_sync(0xffffffffu, m, o));
    __shared__ float sm[4];
    if ((threadIdx.x & 31) == 0) sm[threadIdx.x >> 5] = m;
    __syncthreads();
    float am = fmaxf(fmaxf(sm[0], sm[1]), fmaxf(sm[2], sm[3]));
    float scale = fmaxf(__fdiv_rn(am, FP8_MAX_F), 1e-12f);
    if (threadIdx.x == 0) g_wscale[row] = scale;
    for (int k = threadIdx.x; k < K_DIM; k += 128) {
        float q = rintf(fminf(fmaxf(__fdiv_rn(wr[k], scale), -FP8_MAX_F), FP8_MAX_F));
        g_wq[(size_t)row * K_DIM + k] = __float2half_rn(q);  // exact (integer <= 448)
    }
}

// ---------------- kernel 3: quantize x to fp16 ----------------
__global__ void xq_kernel(const float* __restrict__ x, int n4) {
    float scale = fmaxf(__fdiv_rn(__uint_as_float(g_amax_bits), FP8_MAX_F), 1e-12f);
    const float4* x4 = (const float4*)x;
    int stride = gridDim.x * blockDim.x;
    for (int j = blockIdx.x * blockDim.x + threadIdx.x; j < n4; j += stride) {
        float4 v = x4[j];
        float q0 = rintf(fminf(fmaxf(__fdiv_rn(v.x, scale), -FP8_MAX_F), FP8_MAX_F));
        float q1 = rintf(fminf(fmaxf(__fdiv_rn(v.y, scale), -FP8_MAX_F), FP8_MAX_F));
        float q2 = rintf(fminf(fmaxf(__fdiv_rn(v.z, scale), -FP8_MAX_F), FP8_MAX_F));
        float q3 = rintf(fminf(fmaxf(__fdiv_rn(v.w, scale), -FP8_MAX_F), FP8_MAX_F));
        __half2 h0 = __floats2half2_rn(q0, q1);
        __half2 h1 = __floats2half2_rn(q2, q3);
        uint2 u;
        u.x = *reinterpret_cast<unsigned int*>(&h0);
        u.y = *reinterpret_cast<unsigned int*>(&h1);
        *reinterpret_cast<uint2*>(&g_xq[(size_t)j * 4]) = u;
    }
}

// ---------------- kernel 4: pipelined HMMA GEMM (cp.async + ldmatrix) ----------------
// out[t, o] = acc(t,o) * (iscale * wscale[o]) + bias[o]
__global__ void __launch_bounds__(256, 2)
gemm_kernel(const float* __restrict__ bias, float* __restrict__ out) {
    extern __shared__ __align__(1024) char smem[];
    const uint32_t smem_base = smem_u32(smem);

    const int tid  = threadIdx.x;
    const int wid  = tid >> 5, lane = tid & 31;
    const int wm   = wid >> 2, wn = wid & 3;      // 2x4 warp grid; warp tile 64x32
    const int g    = lane >> 2, t4 = lane & 3;
    const int bm   = blockIdx.y * BM;
    const int bn   = blockIdx.x * BN;

    const __half* Ag = g_xq + (size_t)bm * K_DIM;
    const __half* Bg = g_wq + (size_t)bn * K_DIM;

    // cp.async thread mapping: idx = tid + i*256; row = idx>>3, chunk = idx&7 (16B units)
#define LOAD_TILE(kt, s) do {                                                          \
    uint32_t sb = smem_base + (s) * STAGE_BYTES;                                       \
    _Pragma("unroll")                                                                  \
    for (int i = 0; i < 4; i++) {                                                      \
        int idx = tid + i * 256;                                                       \
        int r = idx >> 3, c = idx & 7;                                                 \
        const __half* ga = Ag + (size_t)r * K_DIM + (kt) * BK + c * 8;                 \
        uint32_t sa = sb + sw128((uint32_t)(r * 128 + c * 16));                        \
        asm volatile("cp.async.cg.shared.global [%0], [%1], 16;" :: "r"(sa), "l"(ga)); \
    }                                                                                  \
    _Pragma("unroll")                                                                  \
    for (int i = 0; i < 4; i++) {                                                      \
        int idx = tid + i * 256;                                                       \
        int r = idx >> 3, c = idx & 7;                                                 \
        const __half* gb = Bg + (size_t)r * K_DIM + (kt) * BK + c * 8;                 \
        uint32_t sa = sb + A_STAGE_BYTES + sw128((uint32_t)(r * 128 + c * 16));        \
        asm volatile("cp.async.cg.shared.global [%0], [%1], 16;" :: "r"(sa), "l"(gb)); \
    }                                                                                  \
    asm volatile("cp.async.commit_group;" ::: "memory");                               \
} while (0)

    // ldmatrix per-lane constants: lane supplies one 16B-row address
    // group = lane>>3: g0 row+0 k+0 | g1 row+8 k+0 | g2 row+0 k+8 | g3 row+8 k+8
    const int rl = (lane & 7) + ((lane >> 3) & 1) * 8;   // row offset 0..15
    const uint32_t cl = (lane >> 4) * 16;                // +8 halves = +16 bytes

    uint32_t rowA[4], xmA[4], rowB[2], xmB[2];
    #pragma unroll
    for (int im = 0; im < 4; im++) {
        rowA[im] = (uint32_t)(wm * 64 + im * 16 + rl) * 128;
        xmA[im]  = (rowA[im] >> 3) & 0x70;
    }
    #pragma unroll
    for (int in2 = 0; in2 < 2; in2++) {
        rowB[in2] = (uint32_t)(wn * 32 + in2 * 16 + rl) * 128 + A_STAGE_BYTES;
        xmB[in2]  = (rowB[in2] >> 3) & 0x70;
    }

    float acc[4][4][4];
    #pragma unroll
    for (int i = 0; i < 4; i++)
        #pragma unroll
        for (int j = 0; j < 4; j++)
            #pragma unroll
            for (int r = 0; r < 4; r++) acc[i][j][r] = 0.f;

    LOAD_TILE(0, 0);
    LOAD_TILE(1, 1);

    for (int kt = 0; kt < NT; kt++) {
        const int s = kt % STAGES;
        if (kt == NT - 1) {
            asm volatile("cp.async.wait_group 0;" ::: "memory");
        } else {
            asm volatile("cp.async.wait_group 1;" ::: "memory");
        }
        __syncthreads();

        const uint32_t stage = smem_base + s * STAGE_BYTES;
        #pragma unroll
        for (int kk8 = 0; kk8 < 4; kk8++) {           // k = kk8*16
            const uint32_t colb = (uint32_t)kk8 * 32 + cl;
            uint32_t a[4][4], bf[2][4];
            #pragma unroll
            for (int im = 0; im < 4; im++) {
                uint32_t ad = stage + rowA[im] + (colb ^ xmA[im]);
                asm volatile("ldmatrix.sync.aligned.m8n8.x4.shared.b16 {%0,%1,%2,%3}, [%4];"
                             : "=r"(a[im][0]), "=r"(a[im][1]), "=r"(a[im][2]), "=r"(a[im][3])
                             : "r"(ad));
            }
            #pragma unroll
            for (int in2 = 0; in2 < 2; in2++) {
                uint32_t ad = stage + rowB[in2] + (colb ^ xmB[in2]);
                asm volatile("ldmatrix.sync.aligned.m8n8.x4.shared.b16 {%0,%1,%2,%3}, [%4];"
                             : "=r"(bf[in2][0]), "=r"(bf[in2][1]), "=r"(bf[in2][2]), "=r"(bf[in2][3])
                             : "r"(ad));
            }
            #pragma unroll
            for (int im = 0; im < 4; im++) {
                #pragma unroll
                for (int in_ = 0; in_ < 4; in_++) {
                    uint32_t b0 = (in_ & 1) ? bf[in_ >> 1][1] : bf[in_ >> 1][0];
                    uint32_t b1 = (in_ & 1) ? bf[in_ >> 1][3] : bf[in_ >> 1][2];
                    float* c = acc[im][in_];
                    asm volatile(
                        "mma.sync.aligned.m16n8k16.row.col.f32.f16.f16.f32 "
                        "{%0,%1,%2,%3}, {%4,%5,%6,%7}, {%8,%9}, {%0,%1,%2,%3};\n"
                        : "+f"(c[0]), "+f"(c[1]), "+f"(c[2]), "+f"(c[3])
                        : "r"(a[im][0]), "r"(a[im][1]), "r"(a[im][2]), "r"(a[im][3]),
                          "r"(b0), "r"(b1));
                }
            }
        }
        __syncthreads();
        if (kt + 2 < NT) LOAD_TILE(kt + 2, (kt + 2) % STAGES);
    }
#undef LOAD_TILE

    // epilogue: dequant + bias
    const float iscale = fmaxf(__fdiv_rn(__uint_as_float(g_amax_bits), FP8_MAX_F), 1e-12f);
    #pragma unroll
    for (int in_ = 0; in_ < 4; in_++) {
        int col = bn + wn * 32 + in_ * 8 + t4 * 2;
        float s0 = iscale * g_wscale[col];
        float s1 = iscale * g_wscale[col + 1];
        float b0 = bias[col];
        float b1 = bias[col + 1];
        #pragma unroll
        for (int im = 0; im < 4; im++) {
            int row = bm + wm * 64 + im * 16 + g;
            float* c = acc[im][in_];
            float2 v0 = make_float2(c[0] * s0 + b0, c[1] * s1 + b1);
            float2 v1 = make_float2(c[2] * s0 + b0, c[3] * s1 + b1);
            *(float2*)&out[(size_t)row * O_DIM + col]       = v0;
            *(float2*)&out[(size_t)(row + 8) * O_DIM + col] = v1;
        }
    }
}

// ---------------- launch ----------------
extern "C" void kernel_launch(void* const* d_in, const int* in_sizes, int n_in,
                              void* d_out, int out_size) {
    const float* x    = (const float*)d_in[0];   // [T, 1024]
    const float* w    = (const float*)d_in[1];   // [1024, 1024]
    const float* bias = (const float*)d_in[2];   // [1024]
    float* out = (float*)d_out;                  // [T, 1024] fp32

    const int n  = in_sizes[0];
    const int n4 = n / 4;
    const int T  = n / K_DIM;                    // 32768

    reset_kernel<<<1, 1>>>();
    amax_kernel<<<1184, 256>>>(x, n4);
    wq_kernel<<<O_DIM, 128>>>(w);
    xq_kernel<<<2048, 256>>>(x, n4);

    static bool attr_set = false;
    if (!attr_set) {
        cudaFuncSetAttribute(gemm_kernel,
                             cudaFuncAttributeMaxDynamicSharedMemorySize, SMEM_TOTAL);
        attr_set = true;
    }
    dim3 grid(O_DIM / BN, T / BM);               // (8, 256)
    gemm_kernel<<<grid, 256, SMEM_TOTAL>>>(bias, out);
}

// round 7
// speedup vs baseline: 1.2828x; 1.0119x over previous
#include <cuda_runtime.h>
#include <cuda_fp16.h>
#include <cstdint>

#define K_DIM 1024
#define O_DIM 1024
#define FP8_MAX_F 448.0f

// ---- GEMM tiling (HMMA mma.sync path; tcgen05 unavailable at compute_103) ----
#define BM 128
#define BN 128
#define BK 64                  // 128 bytes/row fp16 = one SW128 atom
#define STAGES 3
#define NT (K_DIM / BK)        // 16

#define A_STAGE_BYTES (BM * 128)                        // 16384
#define B_STAGE_BYTES (BN * 128)                        // 16384
#define STAGE_BYTES   (A_STAGE_BYTES + B_STAGE_BYTES)   // 32768
#define SMEM_TOTAL    (STAGES * STAGE_BYTES)            // 98304

static __device__ __forceinline__ uint32_t sw128(uint32_t off) {
    return off ^ ((off >> 3) & 0x70);
}
static __device__ __forceinline__ uint32_t smem_u32(const void* p) {
    uint32_t a;
    asm("{ .reg .u64 t; cvta.to.shared.u64 t, %1; cvt.u32.u64 %0, t; }" : "=r"(a) : "l"(p));
    return a;
}

// ---- scratch (static device globals; no runtime allocation) ----
__device__ unsigned int g_amax_bits;
__device__ float  g_wscale[O_DIM];
__device__ __half g_wq[(size_t)O_DIM * K_DIM];
__device__ __half g_xq[(size_t)32768 * K_DIM];

// ---------------- kernel 0: reset ----------------
__global__ void reset_kernel() { g_amax_bits = 0u; }

// ---------------- kernel 1: global amax of x ----------------
__global__ void amax_kernel(const float* __restrict__ x, int n4) {
    const float4* x4 = (const float4*)x;
    float m = 0.f;
    int stride = gridDim.x * blockDim.x;
    for (int j = blockIdx.x * blockDim.x + threadIdx.x; j < n4; j += stride) {
        float4 v = x4[j];
        m = fmaxf(m, fmaxf(fmaxf(fabsf(v.x), fabsf(v.y)), fmaxf(fabsf(v.z), fabsf(v.w))));
    }
    #pragma unroll
    for (int o = 16; o; o >>= 1) m = fmaxf(m, __shfl_xor_sync(0xffffffffu, m, o));
    __shared__ float sm[8];
    if ((threadIdx.x & 31) == 0) sm[threadIdx.x >> 5] = m;
    __syncthreads();
    if (threadIdx.x < 32) {
        m = (threadIdx.x < (blockDim.x >> 5)) ? sm[threadIdx.x] : 0.f;
        #pragma unroll
        for (int o = 4; o; o >>= 1) m = fmaxf(m, __shfl_xor_sync(0xffffffffu, m, o));
        if (threadIdx.x == 0) atomicMax(&g_amax_bits, __float_as_uint(m));
    }
}

// ---------------- kernel 2: per-row weight amax + quantize to fp16 ----------------
__global__ void wq_kernel(const float* __restrict__ w) {
    int row = blockIdx.x;
    const float* wr = w + (size_t)row * K_DIM;
    float m = 0.f;
    for (int k = threadIdx.x; k < K_DIM; k += 128) m = fmaxf(m, fabsf(wr[k]));
    #pragma unroll
    for (int o = 16; o; o >>= 1) m = fmaxf(m, __shfl_xor_sync(0xffffffffu, m, o));
    __shared__ float sm[4];
    if ((threadIdx.x & 31) == 0) sm[threadIdx.x >> 5] = m;
    __syncthreads();
    float am = fmaxf(fmaxf(sm[0], sm[1]), fmaxf(sm[2], sm[3]));
    float scale = fmaxf(__fdiv_rn(am, FP8_MAX_F), 1e-12f);
    if (threadIdx.x == 0) g_wscale[row] = scale;
    for (int k = threadIdx.x; k < K_DIM; k += 128) {
        float q = rintf(fminf(fmaxf(__fdiv_rn(wr[k], scale), -FP8_MAX_F), FP8_MAX_F));
        g_wq[(size_t)row * K_DIM + k] = __float2half_rn(q);  // exact (integer <= 448)
    }
}

// ---------------- kernel 3: quantize x to fp16 (2x float4 per iter for MLP) ----------------
__global__ void xq_kernel(const float* __restrict__ x, int n8) {
    float scale = fmaxf(__fdiv_rn(__uint_as_float(g_amax_bits), FP8_MAX_F), 1e-12f);
    const float4* x4 = (const float4*)x;
    int stride = gridDim.x * blockDim.x;
    for (int j = blockIdx.x * blockDim.x + threadIdx.x; j < n8; j += stride) {
        float4 v0 = x4[j * 2];
        float4 v1 = x4[j * 2 + 1];
        float q[8];
        q[0] = v0.x; q[1] = v0.y; q[2] = v0.z; q[3] = v0.w;
        q[4] = v1.x; q[5] = v1.y; q[6] = v1.z; q[7] = v1.w;
        uint4 u;
        uint32_t* up = (uint32_t*)&u;
        #pragma unroll
        for (int p = 0; p < 4; p++) {
            float a = rintf(fminf(fmaxf(__fdiv_rn(q[p * 2],     scale), -FP8_MAX_F), FP8_MAX_F));
            float b = rintf(fminf(fmaxf(__fdiv_rn(q[p * 2 + 1], scale), -FP8_MAX_F), FP8_MAX_F));
            __half2 h = __floats2half2_rn(a, b);
            up[p] = *reinterpret_cast<unsigned int*>(&h);
        }
        *reinterpret_cast<uint4*>(&g_xq[(size_t)j * 8]) = u;
    }
}

// ---------------- kernel 4: pipelined HMMA GEMM (cp.async + ldmatrix) ----------------
// out[t, o] = acc(t,o) * (iscale * wscale[o]) + bias[o]
__global__ void __launch_bounds__(256, 2)
gemm_kernel(const float* __restrict__ bias, float* __restrict__ out) {
    extern __shared__ __align__(1024) char smem[];
    const uint32_t smem_base = smem_u32(smem);

    const int tid  = threadIdx.x;
    const int wid  = tid >> 5, lane = tid & 31;
    const int wm   = wid >> 2, wn = wid & 3;      // 2x4 warp grid; warp tile 64x32
    const int g    = lane >> 2, t4 = lane & 3;
    const int bm   = blockIdx.y * BM;
    const int bn   = blockIdx.x * BN;

    const __half* Ag = g_xq + (size_t)bm * K_DIM;
    const __half* Bg = g_wq + (size_t)bn * K_DIM;

    // cp.async thread mapping: idx = tid + i*256; row = idx>>3, chunk = idx&7 (16B units)
#define LOAD_TILE(kt, s) do {                                                          \
    uint32_t sb = smem_base + (s) * STAGE_BYTES;                                       \
    _Pragma("unroll")                                                                  \
    for (int i = 0; i < 4; i++) {                                                      \
        int idx = tid + i * 256;                                                       \
        int r = idx >> 3, c = idx & 7;                                                 \
        const __half* ga = Ag + (size_t)r * K_DIM + (kt) * BK + c * 8;                 \
        uint32_t sa = sb + sw128((uint32_t)(r * 128 + c * 16));                        \
        asm volatile("cp.async.cg.shared.global [%0], [%1], 16;" :: "r"(sa), "l"(ga)); \
    }                                                                                  \
    _Pragma("unroll")                                                                  \
    for (int i = 0; i < 4; i++) {                                                      \
        int idx = tid + i * 256;                                                       \
        int r = idx >> 3, c = idx & 7;                                                 \
        const __half* gb = Bg + (size_t)r * K_DIM + (kt) * BK + c * 8;                 \
        uint32_t sa = sb + A_STAGE_BYTES + sw128((uint32_t)(r * 128 + c * 16));        \
        asm volatile("cp.async.cg.shared.global [%0], [%1], 16;" :: "r"(sa), "l"(gb)); \
    }                                                                                  \
    asm volatile("cp.async.commit_group;" ::: "memory");                               \
} while (0)

    // ldmatrix per-lane constants: lane supplies one 16B-row address
    // group = lane>>3: g0 row+0 k+0 | g1 row+8 k+0 | g2 row+0 k+8 | g3 row+8 k+8
    const int rl = (lane & 7) + ((lane >> 3) & 1) * 8;   // row offset 0..15
    const uint32_t cl = (lane >> 4) * 16;                // +8 halves = +16 bytes

    uint32_t rowA[4], xmA[4], rowB[2], xmB[2];
    #pragma unroll
    for (int im = 0; im < 4; im++) {
        rowA[im] = (uint32_t)(wm * 64 + im * 16 + rl) * 128;
        xmA[im]  = (rowA[im] >> 3) & 0x70;
    }
    #pragma unroll
    for (int in2 = 0; in2 < 2; in2++) {
        rowB[in2] = (uint32_t)(wn * 32 + in2 * 16 + rl) * 128 + A_STAGE_BYTES;
        xmB[in2]  = (rowB[in2] >> 3) & 0x70;
    }

    float acc[4][4][4];
    #pragma unroll
    for (int i = 0; i < 4; i++)
        #pragma unroll
        for (int j = 0; j < 4; j++)
            #pragma unroll
            for (int r = 0; r < 4; r++) acc[i][j][r] = 0.f;

    LOAD_TILE(0, 0);
    LOAD_TILE(1, 1);

    for (int kt = 0; kt < NT; kt++) {
        const int s = kt % STAGES;
        if (kt == NT - 1) {
            asm volatile("cp.async.wait_group 0;" ::: "memory");
        } else {
            asm volatile("cp.async.wait_group 1;" ::: "memory");
        }
        // Single barrier per tile. Passing it proves every warp finished
        // compute of tile kt-1, so stage (kt+2)%3 == (kt-1)%3 is reusable.
        __syncthreads();

        if (kt + 2 < NT) LOAD_TILE(kt + 2, (kt + 2) % STAGES);

        const uint32_t stage = smem_base + s * STAGE_BYTES;
        #pragma unroll
        for (int kk8 = 0; kk8 < 4; kk8++) {           // k = kk8*16
            const uint32_t colb = (uint32_t)kk8 * 32 + cl;
            uint32_t a[4][4], bf[2][4];
            #pragma unroll
            for (int im = 0; im < 4; im++) {
                uint32_t ad = stage + rowA[im] + (colb ^ xmA[im]);
                asm volatile("ldmatrix.sync.aligned.m8n8.x4.shared.b16 {%0,%1,%2,%3}, [%4];"
                             : "=r"(a[im][0]), "=r"(a[im][1]), "=r"(a[im][2]), "=r"(a[im][3])
                             : "r"(ad));
            }
            #pragma unroll
            for (int in2 = 0; in2 < 2; in2++) {
                uint32_t ad = stage + rowB[in2] + (colb ^ xmB[in2]);
                asm volatile("ldmatrix.sync.aligned.m8n8.x4.shared.b16 {%0,%1,%2,%3}, [%4];"
                             : "=r"(bf[in2][0]), "=r"(bf[in2][1]), "=r"(bf[in2][2]), "=r"(bf[in2][3])
                             : "r"(ad));
            }
            #pragma unroll
            for (int im = 0; im < 4; im++) {
                #pragma unroll
                for (int in_ = 0; in_ < 4; in_++) {
                    uint32_t b0 = (in_ & 1) ? bf[in_ >> 1][1] : bf[in_ >> 1][0];
                    uint32_t b1 = (in_ & 1) ? bf[in_ >> 1][3] : bf[in_ >> 1][2];
                    float* c = acc[im][in_];
                    asm volatile(
                        "mma.sync.aligned.m16n8k16.row.col.f32.f16.f16.f32 "
                        "{%0,%1,%2,%3}, {%4,%5,%6,%7}, {%8,%9}, {%0,%1,%2,%3};\n"
                        : "+f"(c[0]), "+f"(c[1]), "+f"(c[2]), "+f"(c[3])
                        : "r"(a[im][0]), "r"(a[im][1]), "r"(a[im][2]), "r"(a[im][3]),
                          "r"(b0), "r"(b1));
                }
            }
        }
    }
#undef LOAD_TILE

    // epilogue: dequant + bias
    const float iscale = fmaxf(__fdiv_rn(__uint_as_float(g_amax_bits), FP8_MAX_F), 1e-12f);
    #pragma unroll
    for (int in_ = 0; in_ < 4; in_++) {
        int col = bn + wn * 32 + in_ * 8 + t4 * 2;
        float s0 = iscale * g_wscale[col];
        float s1 = iscale * g_wscale[col + 1];
        float b0 = bias[col];
        float b1 = bias[col + 1];
        #pragma unroll
        for (int im = 0; im < 4; im++) {
            int row = bm + wm * 64 + im * 16 + g;
            float* c = acc[im][in_];
            float2 v0 = make_float2(c[0] * s0 + b0, c[1] * s1 + b1);
            float2 v1 = make_float2(c[2] * s0 + b0, c[3] * s1 + b1);
            *(float2*)&out[(size_t)row * O_DIM + col]       = v0;
            *(float2*)&out[(size_t)(row + 8) * O_DIM + col] = v1;
        }
    }
}

// ---------------- launch ----------------
extern "C" void kernel_launch(void* const* d_in, const int* in_sizes, int n_in,
                              void* d_out, int out_size) {
    const float* x    = (const float*)d_in[0];   // [T, 1024]
    const float* w    = (const float*)d_in[1];   // [1024, 1024]
    const float* bias = (const float*)d_in[2];   // [1024]
    float* out = (float*)d_out;                  // [T, 1024] fp32

    const int n  = in_sizes[0];
    const int n4 = n / 4;
    const int n8 = n / 8;
    const int T  = n / K_DIM;                    // 32768

    reset_kernel<<<1, 1>>>();
    amax_kernel<<<1184, 256>>>(x, n4);
    wq_kernel<<<O_DIM, 128>>>(w);
    xq_kernel<<<2048, 256>>>(x, n8);

    static bool attr_set = false;
    if (!attr_set) {
        cudaFuncSetAttribute(gemm_kernel,
                             cudaFuncAttributeMaxDynamicSharedMemorySize, SMEM_TOTAL);
        attr_set = true;
    }
    dim3 grid(O_DIM / BN, T / BM);               // (8, 256)
    gemm_kernel<<<grid, 256, SMEM_TOTAL>>>(bias, out);
}